// round 11
// baseline (speedup 1.0000x reference)
#include <cuda_runtime.h>

// DerivativeDILATEloss: soft-DTW(gamma=0.01), D[i,j]=(dy_i-dx_j)^2, B=64, n=511.
//
// Round 11: cluster(2) split per batch. 128 CTAs, 256 threads, W=1 row/thread
// (2 warps/SMSP, MUFU floor halved vs R10). Direct 3-ex2 softmin in (m,s)
// form. Intra-CTA warp boundary: local smem mailboxes (free-running).
// Inter-CTA boundary (row 255 -> 256): predicated st.shared::cluster.b64 into
// consumer's smem + st.release.cluster counter; consumer polls locally.
// Dynamic smem padded to 120KB to force 1 CTA/SM. Fused last-CTA reduction.

#define NSEQ   511
#define NBATCH 64
#define NT     256
#define INFV   1.0e9f
#define PADV   1.0e4f
#define INVK   0.0069314718055994531f  // ln(2)/100
#define SQRTK  12.011224298677374f     // sqrt(100/ln2)

// bbuf really needs 8*1024*8 = 64KB; padded to 120KB to cap 1 CTA/SM.
#define SMEM_BYTES (120 * 1024)

__device__ __forceinline__ float ex2f(float x){float r;asm("ex2.approx.f32 %0,%1;":"=f"(r):"f"(x));return r;}
__device__ __forceinline__ float lg2f(float x){float r;asm("lg2.approx.f32 %0,%1;":"=f"(r):"f"(x));return r;}
__device__ __forceinline__ unsigned s2u(const void* p){return (unsigned)__cvta_generic_to_shared(p);}
__device__ __forceinline__ unsigned mapa_u32(unsigned a, unsigned rank){
    unsigned r; asm("mapa.shared::cluster.u32 %0,%1,%2;":"=r"(r):"r"(a),"r"(rank)); return r;
}
template<int OFF>
__device__ __forceinline__ void sts_pair_local(unsigned a, float m, float s, int p){
    asm volatile("{.reg .pred q; setp.ne.u32 q,%0,0; @q st.shared.v2.f32 [%1+%4],{%2,%3};}"
                 ::"r"(p),"r"(a),"f"(m),"f"(s),"n"(OFF):"memory");
}
template<int OFF>
__device__ __forceinline__ void sts_pair_remote(unsigned a, float m, float s, int p){
    asm volatile("{.reg .pred q; .reg .b64 pk; setp.ne.u32 q,%0,0; mov.b64 pk,{%2,%3};"
                 " @q st.shared::cluster.b64 [%1+%4],pk;}"
                 ::"r"(p),"r"(a),"f"(m),"f"(s),"n"(OFF):"memory");
}
__device__ __forceinline__ void strel_cluster(unsigned a, int v, int p){
    asm volatile("{.reg .pred q; setp.ne.u32 q,%0,0; @q st.release.cluster.shared::cluster.b32 [%1],%2;}"
                 ::"r"(p),"r"(a),"r"(v):"memory");
}
__device__ __forceinline__ int ld_acq_cluster(unsigned a){
    int v; asm volatile("ld.acquire.cluster.shared.b32 %0,[%1];":"=r"(v):"r"(a):"memory"); return v;
}

__device__ float g_partial[NBATCH];
__device__ int   g_done = 0;

__global__ __launch_bounds__(NT, 1) __cluster_dims__(2, 1, 1)
void sdtw_kernel(const float* __restrict__ input,
                 const float* __restrict__ target,
                 float* __restrict__ out)
{
    __shared__ float sdxp[1536];   // padded scaled dx, logical base 512
    __shared__ int   cnt[16];      // [0..7] producer progress, [15] sentinel
    __shared__ int   slast;
    extern __shared__ float2 bbuf[];   // [8][1024]; row 7: remote (rank1) / dummy (rank0)

    const int t = threadIdx.x, w = t >> 5, lane = t & 31;
    unsigned rank; asm("mov.u32 %0, %%cluster_ctarank;" : "=r"(rank));
    const int b = blockIdx.x >> 1;

    const float* in_b = input  + b * 512;
    const float* tg_b = target + b * 512;

    #pragma unroll
    for (int rep = 0; rep < 6; ++rep) {
        int idx = t + rep * NT, q = idx - 512;
        float v = PADV;
        if (q >= 0 && q < NSEQ) v = (in_b[q + 1] - in_b[q]) * SQRTK;
        sdxp[idx] = v;
    }
    #pragma unroll
    for (int rep = 0; rep < 4; ++rep)          // row 7 init: (INF, 1)
        bbuf[7 * 1024 + t + rep * NT] = make_float2(INFV, 1.0f);
    if (t < 16) cnt[t] = (t == 15) ? 0x7FFFFFFF : 0;
    if (t == 0) slast = 0;
    __syncthreads();
    asm volatile("barrier.cluster.arrive.aligned;" ::: "memory");
    asm volatile("barrier.cluster.wait.aligned;"   ::: "memory");

    const int i = (int)rank * 256 + t;         // global row owned by this thread
    const float dyr = (i >= 1) ? (tg_b[i] - tg_b[i - 1]) * SQRTK : 0.0f;

    // state (m,s): value = m - log2(s)
    float r1m = INFV, r1s = 1.0f;              // own row @ diag d-1
    float am  = (i == 1) ? 0.0f : INFV;        // row i-1 @ diag d-2 (R[0,0]=0 seed)
    float as_ = 1.0f;
    float mbm = INFV, mbs = 1.0f;              // lane-0 boundary @ diag d-1
    const float* dxp = sdxp + 512 - i - 1;     // dxp[d] = scaled dx[j-1]
    float dxv = dxp[2];

    const float2* subrow = bbuf + ((w == 0) ? 7 : (w - 1)) * 1024;
    unsigned cntp_a = (w == 0) ? ((rank == 1) ? s2u(&cnt[7]) : s2u(&cnt[15]))
                               : s2u(&cnt[w - 1]);
    unsigned pub_la = s2u(&bbuf[((w < 7) ? w : 0) * 1024]) + 16u;   // slot d0=2
    unsigned pub_ra = mapa_u32(s2u(&bbuf[7 * 1024]) + 16u, 1u);
    unsigned cnt_sa = (w < 7) ? mapa_u32(s2u(&cnt[w]), rank)
                              : mapa_u32(s2u(&cnt[7]), 1u);
    const int ploc = (lane == 31 && w < 7) ? 1 : 0;
    const int prem = (lane == 31 && w == 7 && rank == 0) ? 1 : 0;
    const int pcnt = (lane == 31 && (w < 7 || rank == 0)) ? 1 : 0;
    int cc = 0;

    #pragma unroll 1
    for (int d0 = 2; d0 <= 1018; d0 += 4) {
        const int need = d0 + 3;
        if (cc < need) { do { cc = ld_acq_cluster(cntp_a); } while (cc < need); }

        const float4 bl0 = *reinterpret_cast<const float4*>(subrow + d0);
        const float4 bl1 = *reinterpret_cast<const float4*>(subrow + d0 + 2);

        #pragma unroll
        for (int u = 0; u < 4; ++u) {
            const int d = d0 + u;
            const float shm = __shfl_up_sync(0xFFFFFFFFu, r1m, 1);
            const float shs = __shfl_up_sync(0xFFFFFFFFu, r1s, 1);
            const float um = (lane == 0) ? mbm : shm;
            const float us = (lane == 0) ? mbs : shs;

            const float mnm = fminf(fminf(am, um), r1m);
            const float x1 = ex2f(mnm - am);
            const float x2 = ex2f(mnm - um);
            const float x3 = ex2f(mnm - r1m);
            float ns = fmaf(as_, x1, fmaf(us, x2, r1s * x3));
            const float dv = dyr - dxv;
            float nm = fmaf(dv, dv, mnm);

            if (u == 3) {   // exact power-of-2 renorm of s into m
                unsigned sb = __float_as_uint(ns);
                int e = (int)(sb >> 23) - 127;
                ns = __uint_as_float((sb & 0x007FFFFFu) | 0x3F800000u);
                nm -= (float)e;
            }

            if (u == 0) { sts_pair_local<0 >(pub_la, nm, ns, ploc); sts_pair_remote<0 >(pub_ra, nm, ns, prem); }
            if (u == 1) { sts_pair_local<8 >(pub_la, nm, ns, ploc); sts_pair_remote<8 >(pub_ra, nm, ns, prem); }
            if (u == 2) { sts_pair_local<16>(pub_la, nm, ns, ploc); sts_pair_remote<16>(pub_ra, nm, ns, prem); }
            if (u == 3) { sts_pair_local<24>(pub_la, nm, ns, ploc); sts_pair_remote<24>(pub_ra, nm, ns, prem);
                          strel_cluster(cnt_sa, d, pcnt); }

            am = um; as_ = us;
            r1m = nm; r1s = ns;
            dxv = dxp[d + 1];
            mbm = (u == 0) ? bl0.x : (u == 1) ? bl0.z : (u == 2) ? bl1.x : bl1.z;
            mbs = (u == 0) ? bl0.y : (u == 1) ? bl0.w : (u == 2) ? bl1.y : bl1.w;
        }
        pub_la += 32u;
        pub_ra += 32u;
    }

    // tail step d = 1022 (no publish/poll)
    float resm, ress;
    {
        const float shm = __shfl_up_sync(0xFFFFFFFFu, r1m, 1);
        const float shs = __shfl_up_sync(0xFFFFFFFFu, r1s, 1);
        const float um = (lane == 0) ? mbm : shm;
        const float us = (lane == 0) ? mbs : shs;
        const float mnm = fminf(fminf(am, um), r1m);
        const float x1 = ex2f(mnm - am);
        const float x2 = ex2f(mnm - um);
        const float x3 = ex2f(mnm - r1m);
        ress = fmaf(as_, x1, fmaf(us, x2, r1s * x3));
        const float dv = dyr - dxv;
        resm = fmaf(dv, dv, mnm);
    }

    // fused reduction: last rank-1 CTA sums g_partial and writes out
    if (rank == 1 && t == NT - 1) {            // global row 511
        g_partial[b] = (resm - lg2f(ress)) * INVK;
        __threadfence();
        int prev = atomicAdd(&g_done, 1);
        slast = (prev == NBATCH - 1) ? 1 : 0;
    }
    __syncthreads();
    if (slast && t < 32) {
        __threadfence();
        float s = g_partial[t] + g_partial[t + 32];
        #pragma unroll
        for (int o = 16; o > 0; o >>= 1)
            s += __shfl_down_sync(0xFFFFFFFFu, s, o);
        if (t == 0) { out[0] = s * (1.0f / (float)NBATCH); g_done = 0; }
    }
}

extern "C" void kernel_launch(void* const* d_in, const int* in_sizes, int n_in,
                              void* d_out, int out_size)
{
    const float* input  = (const float*)d_in[0];
    const float* target = (const float*)d_in[1];
    float* out = (float*)d_out;

    cudaFuncSetAttribute(sdtw_kernel,
                         cudaFuncAttributeMaxDynamicSharedMemorySize, SMEM_BYTES);
    sdtw_kernel<<<2 * NBATCH, NT, SMEM_BYTES>>>(input, target, out);
}

// round 12
// speedup vs baseline: 1.1486x; 1.1486x over previous
#include <cuda_runtime.h>

// DerivativeDILATEloss: soft-DTW(gamma=0.01), D[i,j]=(dy_i-dx_j)^2, B=64, n=511.
//
// Round 12: cluster(2) split per batch, W=1 row/thread, 256 thr/CTA, 128 CTAs.
// ALL intra-CTA coupling is cta-scope (R10 machinery). Cluster-scope ops only
// on the single inter-CTA edge (rank0-w7 -> rank1-w0), inside warp-uniform
// branches, batched per 4-step block. Publishes batched as v4 stores.
// Direct 3-ex2 softmin in (m,s) form; dx padding for validity; fused reduction.

#define NSEQ   511
#define NBATCH 64
#define NT     256
#define INFV   1.0e9f
#define PADV   1.0e4f
#define INVK   0.0069314718055994531f  // ln(2)/100
#define SQRTK  12.011224298677374f     // sqrt(100/ln2)

// bbuf = 8*1024*float2 = 64KB; padded to 120KB to force 1 CTA/SM.
#define SMEM_BYTES (120 * 1024)

__device__ __forceinline__ float ex2f(float x){float r;asm("ex2.approx.f32 %0,%1;":"=f"(r):"f"(x));return r;}
__device__ __forceinline__ float lg2f(float x){float r;asm("lg2.approx.f32 %0,%1;":"=f"(r):"f"(x));return r;}
__device__ __forceinline__ unsigned s2u(const void* p){return (unsigned)__cvta_generic_to_shared(p);}
__device__ __forceinline__ unsigned mapa_u32(unsigned a, unsigned rank){
    unsigned r; asm("mapa.shared::cluster.u32 %0,%1,%2;":"=r"(r):"r"(a),"r"(rank)); return r;
}
template<int OFF>
__device__ __forceinline__ void sts_v4_pred(unsigned a, float x, float y, float z, float w, int p){
    asm volatile("{.reg .pred q; setp.ne.u32 q,%0,0; @q st.shared.v4.f32 [%1+%6],{%2,%3,%4,%5};}"
                 ::"r"(p),"r"(a),"f"(x),"f"(y),"f"(z),"f"(w),"n"(OFF):"memory");
}
template<int OFF>
__device__ __forceinline__ void sts_b64_remote(unsigned a, float m, float s, int p){
    asm volatile("{.reg .pred q; .reg .b64 pk; setp.ne.u32 q,%0,0; mov.b64 pk,{%2,%3};"
                 " @q st.shared::cluster.b64 [%1+%4],pk;}"
                 ::"r"(p),"r"(a),"f"(m),"f"(s),"n"(OFF):"memory");
}
__device__ __forceinline__ void strel_pred(unsigned a, int v, int p){
    asm volatile("{.reg .pred q; setp.ne.u32 q,%0,0; @q st.release.cta.shared.b32 [%1],%2;}"
                 ::"r"(p),"r"(a),"r"(v):"memory");
}
__device__ __forceinline__ void strel_cluster_pred(unsigned a, int v, int p){
    asm volatile("{.reg .pred q; setp.ne.u32 q,%0,0; @q st.release.cluster.shared::cluster.b32 [%1],%2;}"
                 ::"r"(p),"r"(a),"r"(v):"memory");
}
__device__ __forceinline__ int ld_acq(unsigned a){
    int v; asm volatile("ld.acquire.cta.shared.b32 %0,[%1];":"=r"(v):"r"(a):"memory"); return v;
}
__device__ __forceinline__ int ld_acq_cluster(unsigned a){
    int v; asm volatile("ld.acquire.cluster.shared.b32 %0,[%1];":"=r"(v):"r"(a):"memory"); return v;
}

__device__ float g_partial[NBATCH];
__device__ int   g_done = 0;

__global__ __launch_bounds__(NT, 1) __cluster_dims__(2, 1, 1)
void sdtw_kernel(const float* __restrict__ input,
                 const float* __restrict__ target,
                 float* __restrict__ out)
{
    __shared__ float sdxp[1536];   // padded scaled dx, logical base 512
    __shared__ int   cnt[16];      // [0..6] local producers, [7] remote edge, [15] sentinel
    __shared__ int   slast;
    extern __shared__ float2 bbuf[];   // [8][1024]; row w = producer warp w; row 7 = incoming edge / dummy

    const int t = threadIdx.x, w = t >> 5, lane = t & 31;
    unsigned rank; asm("mov.u32 %0, %%cluster_ctarank;" : "=r"(rank));
    const int b = blockIdx.x >> 1;

    const float* in_b = input  + b * 512;
    const float* tg_b = target + b * 512;

    #pragma unroll
    for (int rep = 0; rep < 6; ++rep) {
        int idx = t + rep * NT, q = idx - 512;
        float v = PADV;
        if (q >= 0 && q < NSEQ) v = (in_b[q + 1] - in_b[q]) * SQRTK;
        sdxp[idx] = v;
    }
    if (rank == 0) {
        #pragma unroll
        for (int rep = 0; rep < 4; ++rep)      // rank0 row 7 = dummy (INF,1)
            bbuf[7 * 1024 + t + rep * NT] = make_float2(INFV, 1.0f);
    }
    if (t < 16) cnt[t] = (t == 15) ? 0x7FFFFFFF : 0;
    if (t == 0) slast = 0;
    __syncthreads();
    asm volatile("barrier.cluster.arrive.aligned;" ::: "memory");
    asm volatile("barrier.cluster.wait.aligned;"   ::: "memory");

    const int i = (int)rank * 256 + t;         // global row
    const float dyr = (i >= 1) ? (tg_b[i] - tg_b[i - 1]) * SQRTK : 0.0f;

    float r1m = INFV, r1s = 1.0f;              // own row @ diag d-1
    float am  = (i == 1) ? 0.0f : INFV;        // row i-1 @ diag d-2 (R[0,0] seed)
    float as_ = 1.0f;
    float mbm = INFV, mbs = 1.0f;              // lane-0 boundary @ diag d-1
    const float* dxp = sdxp + 512 - i - 1;
    float dxv = dxp[2];

    const float2* subrow = bbuf + ((w == 0) ? 7 : (w - 1)) * 1024;
    const unsigned cntp_a = (w == 0) ? ((rank == 1) ? s2u(&cnt[7]) : s2u(&cnt[15]))
                                     : s2u(&cnt[w - 1]);
    unsigned pub_la = s2u(&bbuf[((w < 7) ? w : 0) * 1024]) + 16u;   // slot d0=2
    const unsigned cnt_a = s2u(&cnt[w]);
    unsigned pub_ra = 0, cnt_ra = 0;
    const bool ep = (w == 7 && rank == 0);     // edge producer warp
    const bool ec = (w == 0 && rank == 1);     // edge consumer warp
    if (ep) {
        pub_ra = mapa_u32(s2u(&bbuf[7 * 1024]), 1u) + 16u;
        cnt_ra = mapa_u32(s2u(&cnt[7]), 1u);
    }
    const int ploc = (lane == 31 && w < 7) ? 1 : 0;
    const int p31  = (lane == 31) ? 1 : 0;
    int cc = 0;

    float pm0, ps0, pm1, ps1, pm2, ps2, pm3, ps3;

    #pragma unroll 1
    for (int d0 = 2; d0 <= 1018; d0 += 4) {
        const int need = d0 + 3;
        if (cc < need) {
            if (ec) { do { cc = ld_acq_cluster(cntp_a); } while (cc < need); }
            else    { do { cc = ld_acq(cntp_a);         } while (cc < need); }
        }

        const float4 bl0 = *reinterpret_cast<const float4*>(subrow + d0);
        const float4 bl1 = *reinterpret_cast<const float4*>(subrow + d0 + 2);

        #pragma unroll
        for (int u = 0; u < 4; ++u) {
            const float shm = __shfl_up_sync(0xFFFFFFFFu, r1m, 1);
            const float shs = __shfl_up_sync(0xFFFFFFFFu, r1s, 1);
            const float um = (lane == 0) ? mbm : shm;
            const float us = (lane == 0) ? mbs : shs;

            const float mnm = fminf(fminf(am, um), r1m);
            const float x1 = ex2f(mnm - am);
            const float x2 = ex2f(mnm - um);
            const float x3 = ex2f(mnm - r1m);
            float ns = fmaf(as_, x1, fmaf(us, x2, r1s * x3));
            const float dv = dyr - dxv;
            float nm = fmaf(dv, dv, mnm);

            if (u == 3) {   // exact power-of-2 renorm of s into m
                unsigned sb = __float_as_uint(ns);
                int e = (int)(sb >> 23) - 127;
                ns = __uint_as_float((sb & 0x007FFFFFu) | 0x3F800000u);
                nm -= (float)e;
            }

            if (u == 0) { pm0 = nm; ps0 = ns; }
            if (u == 1) { pm1 = nm; ps1 = ns; }
            if (u == 2) { pm2 = nm; ps2 = ns; }
            if (u == 3) { pm3 = nm; ps3 = ns; }

            am = um; as_ = us;
            r1m = nm; r1s = ns;
            dxv = dxp[d0 + u + 1];
            mbm = (u == 0) ? bl0.x : (u == 1) ? bl0.z : (u == 2) ? bl1.x : bl1.z;
            mbs = (u == 0) ? bl0.y : (u == 1) ? bl0.w : (u == 2) ? bl1.y : bl1.w;
        }

        // local publish (uniform, predicated): slots d0..d0+3 + counter
        sts_v4_pred<0 >(pub_la, pm0, ps0, pm1, ps1, ploc);
        sts_v4_pred<16>(pub_la, pm2, ps2, pm3, ps3, ploc);
        strel_pred(cnt_a, need, ploc);
        pub_la += 32u;

        // inter-CTA edge publish (warp-uniform branch: only rank0-w7 enters)
        if (ep) {
            sts_b64_remote<0 >(pub_ra, pm0, ps0, p31);
            sts_b64_remote<8 >(pub_ra, pm1, ps1, p31);
            sts_b64_remote<16>(pub_ra, pm2, ps2, p31);
            sts_b64_remote<24>(pub_ra, pm3, ps3, p31);
            const int dopub = ((((d0 + 2) & 7) == 0) || d0 == 1018) ? p31 : 0;
            strel_cluster_pred(cnt_ra, need, dopub);
            pub_ra += 32u;
        }
    }

    // tail step d = 1022 (no publish/poll)
    float resm, ress;
    {
        const float shm = __shfl_up_sync(0xFFFFFFFFu, r1m, 1);
        const float shs = __shfl_up_sync(0xFFFFFFFFu, r1s, 1);
        const float um = (lane == 0) ? mbm : shm;
        const float us = (lane == 0) ? mbs : shs;
        const float mnm = fminf(fminf(am, um), r1m);
        const float x1 = ex2f(mnm - am);
        const float x2 = ex2f(mnm - um);
        const float x3 = ex2f(mnm - r1m);
        ress = fmaf(as_, x1, fmaf(us, x2, r1s * x3));
        const float dv = dyr - dxv;
        resm = fmaf(dv, dv, mnm);
    }

    // fused reduction: global row 511 writes partial; last arriving CTA reduces
    if (rank == 1 && t == NT - 1) {
        g_partial[b] = (resm - lg2f(ress)) * INVK;
        __threadfence();
        int prev = atomicAdd(&g_done, 1);
        slast = (prev == NBATCH - 1) ? 1 : 0;
    }
    __syncthreads();
    if (slast && t < 32) {
        __threadfence();
        float s = g_partial[t] + g_partial[t + 32];
        #pragma unroll
        for (int o = 16; o > 0; o >>= 1)
            s += __shfl_down_sync(0xFFFFFFFFu, s, o);
        if (t == 0) { out[0] = s * (1.0f / (float)NBATCH); g_done = 0; }
    }
}

extern "C" void kernel_launch(void* const* d_in, const int* in_sizes, int n_in,
                              void* d_out, int out_size)
{
    const float* input  = (const float*)d_in[0];
    const float* target = (const float*)d_in[1];
    float* out = (float*)d_out;

    cudaFuncSetAttribute(sdtw_kernel,
                         cudaFuncAttributeMaxDynamicSharedMemorySize, SMEM_BYTES);
    sdtw_kernel<<<2 * NBATCH, NT, SMEM_BYTES>>>(input, target, out);
}